// round 16
// baseline (speedup 1.0000x reference)
#include <cuda_runtime.h>
#include <cuda_bf16.h>

#define TT 2048
#define BB 4096
#define NTH 128
#define NCTA 128

typedef unsigned long long u64;
typedef unsigned int u32;
typedef unsigned short u16;

static __device__ __forceinline__ u64 pk2(float x, float y){
    u64 r; asm("mov.b64 %0,{%1,%2};" : "=l"(r) : "f"(x), "f"(y)); return r;
}
static __device__ __forceinline__ void up2(u64 v, float &x, float &y){
    asm("mov.b64 {%0,%1},%2;" : "=f"(x), "=f"(y) : "l"(v));
}
static __device__ __forceinline__ u64 add2(u64 a, u64 b){
    u64 d; asm("add.rn.f32x2 %0,%1,%2;" : "=l"(d) : "l"(a), "l"(b)); return d;
}
static __device__ __forceinline__ float pick4(float a, float b, float c, float d, int s){
    float x = (s & 1) ? b : a;
    float y = (s & 1) ? d : c;
    return (s & 2) ? y : x;
}
static __device__ __forceinline__ u32 bfpack(float lo, float hi){
    u32 r; asm("cvt.rn.bf16x2.f32 %0, %1, %2;" : "=r"(r) : "f"(hi), "f"(lo)); return r;
}
static __device__ __forceinline__ void mma16816(
    float &c0, float &c1, float &c2, float &c3,
    u32 a0, u32 a1, u32 a2, u32 a3, u32 b0, u32 b1)
{
    asm("mma.sync.aligned.m16n8k16.row.col.f32.bf16.bf16.f32 "
        "{%0,%1,%2,%3},{%4,%5,%6,%7},{%8,%9},{%0,%1,%2,%3};"
        : "+f"(c0), "+f"(c1), "+f"(c2), "+f"(c3)
        : "r"(a0), "r"(a1), "r"(a2), "r"(a3), "r"(b0), "r"(b1));
}

__global__ __launch_bounds__(NTH, 1)
void garch_pinn_kernel(
    const float* __restrict__ returns, const float* __restrict__ log_rv,
    const float* __restrict__ omega_p, const float* __restrict__ beta_p,
    const float* __restrict__ tau1_p, const float* __restrict__ tau2_p,
    const float* __restrict__ gamma_p, const float* __restrict__ xi_p,
    const float* __restrict__ phi_p, const float* __restrict__ d1_p,
    const float* __restrict__ d2_p, const float* __restrict__ mu_p,
    const float* __restrict__ W1, const float* __restrict__ b1,
    const float* __restrict__ W2, const float* __restrict__ b2,
    const float* __restrict__ W3, const float* __restrict__ b3_p,
    float* __restrict__ out)
{
    // bf16 h tiles: [warp][group][chain][i pad 80]
    __shared__ u16 hsm[4][2][4][80];                  // 5 KB
    // output staging: [warp][group*16 + arr*4+b][33]
    __shared__ float obuf[4][32][33];                 // 17 KB

    const int tid = threadIdx.x;
    const int w = tid >> 5;
    const int l = tid & 31;
    const int r = l >> 2;          // mma fragment row group
    const int kq = (l & 3) * 2;    // mma fragment k / col pair base

    // ---- A fragments (A[m][k] = W2[k][m]) preloaded, SHARED by both groups ----
    u32 afr[4][4][4];
    #pragma unroll
    for (int mt = 0; mt < 4; mt++) {
        #pragma unroll
        for (int kt = 0; kt < 4; kt++) {
            const int m0 = 16 * mt + r, k0 = 16 * kt + kq;
            afr[mt][kt][0] = bfpack(W2[k0 * 64 + m0],           W2[(k0 + 1) * 64 + m0]);
            afr[mt][kt][1] = bfpack(W2[k0 * 64 + m0 + 8],       W2[(k0 + 1) * 64 + m0 + 8]);
            afr[mt][kt][2] = bfpack(W2[(k0 + 8) * 64 + m0],     W2[(k0 + 9) * 64 + m0]);
            afr[mt][kt][3] = bfpack(W2[(k0 + 8) * 64 + m0 + 8], W2[(k0 + 9) * 64 + m0 + 8]);
        }
    }
    float b2lo[4], b2hi[4], w3lo[4], w3hi[4];
    #pragma unroll
    for (int mt = 0; mt < 4; mt++) {
        b2lo[mt] = b2[16 * mt + r];     b2hi[mt] = b2[16 * mt + r + 8];
        w3lo[mt] = W3[16 * mt + r];     w3hi[mt] = W3[16 * mt + r + 8];
    }

    // layer-1 constants: lane computes rows 2l, 2l+1 (packed STS.32)
    const float w1a0 = W1[0 * 64 + 2 * l],     w1a1 = W1[1 * 64 + 2 * l],     w1a2 = W1[2 * 64 + 2 * l];
    const float w1b0 = W1[0 * 64 + 2 * l + 1], w1b1 = W1[1 * 64 + 2 * l + 1], w1b2 = W1[2 * 64 + 2 * l + 1];
    const float b1a = b1[2 * l], b1b = b1[2 * l + 1];

    const float omega = *omega_p, beta = *beta_p, tau1 = *tau1_p, tau2 = *tau2_p;
    const float gam = *gamma_p, xi = *xi_p, phi = *phi_p;
    const float d1 = *d1_p, d2 = *d2_p, mu = *mu_p, b3 = *b3_p;
    const float beta001 = beta * 0.01f;
    const float C0 = fmaf(beta001, b3, omega);

    // this warp's 8 chains = 2 groups of 4
    const long bg = (long)blockIdx.x * 32 + w * 8;
    const float* rp = returns + bg * TT;
    const float* lp = log_rv + bg * TT;
    const long BT = (long)BB * TT;

    float lh[8], rcur[8], lcur[8];
    #pragma unroll
    for (int i = 0; i < 8; i++) {
        lh[i] = lp[i * TT];
        rcur[i] = rp[i * TT];
        lcur[i] = lh[i];
    }

    u16* hw0 = &hsm[w][0][0][0];
    u16* hw1 = &hsm[w][1][0][0];
    const u16* brow0 = &hsm[w][0][r & 3][kq];
    const u16* brow1 = &hsm[w][1][r & 3][kq];
    float* obw = &obuf[w][0][0];

    for (int t = 0; t < TT; t++) {
        // ---- measurement + recurrence base, both groups (independent ILP) ----
        float z[8], u[8], base[8];
        #pragma unroll
        for (int i = 0; i < 8; i++) {
            float e = __expf(-0.5f * lh[i]);
            z[i] = (rcur[i] - mu) * e;
            float z2m1 = z[i] * z[i] - 1.0f;
            float s = xi + phi * lh[i] + d1 * z[i] + d2 * z2m1;
            u[i] = lcur[i] - s;              // log_x == lcur exactly
            float nb = fmaf(beta, lh[i], C0);
            nb = fmaf(tau1, z[i], nb);
            nb = fmaf(tau2, z2m1, nb);
            base[i] = fmaf(gam, u[i], nb);
        }

        // ---- layer 1: rows 2l,2l+1, 8 chains -> packed bf16x2 STS.32 ----
        #pragma unroll
        for (int i = 0; i < 8; i++) {
            float t0 = fmaf(w1a0, lh[i], b1a);
            t0 = fmaf(w1a1, z[i], t0);
            t0 = fmaf(w1a2, u[i], t0);
            float t1 = fmaf(w1b0, lh[i], b1b);
            t1 = fmaf(w1b1, z[i], t1);
            t1 = fmaf(w1b2, u[i], t1);
            u16* dst = (i < 4) ? hw0 : hw1;
            *reinterpret_cast<u32*>(dst + (i & 3) * 80 + 2 * l) =
                bfpack(fmaxf(t0, 0.0f), fmaxf(t1, 0.0f));
        }

        // stage lx/z/u for both groups (lanes 4..15)
        if (l >= 4 && l < 16) {
            const int bsel = l & 3;
            #pragma unroll
            for (int g = 0; g < 2; g++) {
                const float* zz = z + 4 * g;
                const float* uu = u + 4 * g;
                const float* ll = lcur + 4 * g;
                float v_lx = pick4(ll[0], ll[1], ll[2], ll[3], bsel);
                float v_z  = pick4(zz[0], zz[1], zz[2], zz[3], bsel);
                float v_u  = pick4(uu[0], uu[1], uu[2], uu[3], bsel);
                float v = pick4(v_lx, v_lx, v_z, v_u, l >> 2);
                obw[(g * 16 + l) * 33 + (t & 31)] = v;
            }
        }
        __syncwarp();

        // ---- B fragments, both groups ----
        u32 bfr[2][4][2];
        #pragma unroll
        for (int kt = 0; kt < 4; kt++) {
            bfr[0][kt][0] = *reinterpret_cast<const u32*>(brow0 + 16 * kt);
            bfr[0][kt][1] = *reinterpret_cast<const u32*>(brow0 + 16 * kt + 8);
            bfr[1][kt][0] = *reinterpret_cast<const u32*>(brow1 + 16 * kt);
            bfr[1][kt][1] = *reinterpret_cast<const u32*>(brow1 + 16 * kt + 8);
        }

        // ---- prefetch next-step inputs (hidden under tensor work) ----
        const int tn = (t + 1 < TT) ? t + 1 : t;
        float rnxt[8], lnxt[8];
        #pragma unroll
        for (int i = 0; i < 8; i++) { rnxt[i] = rp[i * TT + tn]; lnxt[i] = lp[i * TT + tn]; }

        // ---- layer 2 on tensor pipe: 8 independent (g,mt) HMMA chains ----
        float cf[2][4][4];
        #pragma unroll
        for (int mt = 0; mt < 4; mt++) {
            #pragma unroll
            for (int g = 0; g < 2; g++) {
                cf[g][mt][0] = b2lo[mt]; cf[g][mt][1] = b2lo[mt];
                cf[g][mt][2] = b2hi[mt]; cf[g][mt][3] = b2hi[mt];
                #pragma unroll
                for (int kt = 0; kt < 4; kt++)
                    mma16816(cf[g][mt][0], cf[g][mt][1], cf[g][mt][2], cf[g][mt][3],
                             afr[mt][kt][0], afr[mt][kt][1], afr[mt][kt][2], afr[mt][kt][3],
                             bfr[g][kt][0], bfr[g][kt][1]);
            }
        }

        // ---- layer 3 epilogue + reduce, both groups interleaved ----
        u64 pair[2];
        #pragma unroll
        for (int g = 0; g < 2; g++) {
            float pe = 0.0f, po = 0.0f;
            #pragma unroll
            for (int mt = 0; mt < 4; mt++) {
                pe = fmaf(fmaxf(cf[g][mt][0], 0.0f), w3lo[mt], pe);
                pe = fmaf(fmaxf(cf[g][mt][2], 0.0f), w3hi[mt], pe);
                po = fmaf(fmaxf(cf[g][mt][1], 0.0f), w3lo[mt], po);
                po = fmaf(fmaxf(cf[g][mt][3], 0.0f), w3hi[mt], po);
            }
            pair[g] = pk2(pe, po);
        }
        #pragma unroll
        for (int s = 4; s <= 16; s <<= 1) {
            pair[0] = add2(pair[0], __shfl_xor_sync(0xffffffffu, pair[0], s));
            pair[1] = add2(pair[1], __shfl_xor_sync(0xffffffffu, pair[1], s));
        }
        float tot[8];
        #pragma unroll
        for (int g = 0; g < 2; g++) {
            u64 other = __shfl_xor_sync(0xffffffffu, pair[g], 1);
            float mx, my, ox, oy;
            up2(pair[g], mx, my);
            up2(other, ox, oy);
            const bool oddc = (l & 1);
            tot[4 * g + 0] = oddc ? ox : mx;  tot[4 * g + 1] = oddc ? oy : my;
            tot[4 * g + 2] = oddc ? mx : ox;  tot[4 * g + 3] = oddc ? my : oy;
        }

        // stage enh (lanes 0-3, both groups): needs OLD lh
        if (l < 4) {
            obw[l * 33 + (t & 31)]        = fmaf(0.01f, tot[l] + b3, lh[l]);
            obw[(16 + l) * 33 + (t & 31)] = fmaf(0.01f, tot[4 + l] + b3, lh[4 + l]);
        }

        // ---- recurrence: single fma per chain ----
        #pragma unroll
        for (int i = 0; i < 8; i++) {
            lh[i] = fmaf(beta001, tot[i], base[i]);
            rcur[i] = rnxt[i];
            lcur[i] = lnxt[i];
        }

        // ---- flush every 32 steps: 32 rows (2 groups x enh,lx,z,u x 4) ----
        if ((t & 31) == 31) {
            const int t0 = t - 31;
            #pragma unroll
            for (int q = 0; q < 32; q++) {
                const int g = q >> 4, qq = q & 15;
                const int arr = qq >> 2, bsel = qq & 3;
                out[(long)arr * BT + (bg + 4 * g + bsel) * TT + t0 + l] = obw[q * 33 + l];
            }
        }
        __syncwarp();
    }
}

extern "C" void kernel_launch(void* const* d_in, const int* in_sizes, int n_in,
                              void* d_out, int out_size)
{
    garch_pinn_kernel<<<NCTA, NTH>>>(
        (const float*)d_in[0],  (const float*)d_in[1],
        (const float*)d_in[2],  (const float*)d_in[3],
        (const float*)d_in[4],  (const float*)d_in[5],
        (const float*)d_in[6],  (const float*)d_in[7],
        (const float*)d_in[8],  (const float*)d_in[9],
        (const float*)d_in[10], (const float*)d_in[11],
        (const float*)d_in[12], (const float*)d_in[13],
        (const float*)d_in[14], (const float*)d_in[15],
        (const float*)d_in[16], (const float*)d_in[17],
        (float*)d_out);
}